// round 6
// baseline (speedup 1.0000x reference)
#include <cuda_runtime.h>
#include <math.h>

#define BATCH 256
#define NT_OUT 32768
#define OUT_ELEMS (32u * 3u * 32768u * 8u)   // 25,165,824

// scratch — __device__ globals, no allocs
__device__ float g_bufA[BATCH * 64 * 2048];
__device__ float g_bufB[BATCH * 64 * 2048];
__device__ float g_wprep[131072];
__device__ double g_loss_accum;
__device__ int    g_mask[BATCH];

typedef unsigned long long u64;

__device__ __forceinline__ void fma2(u64 &d, u64 a, u64 b) {
    asm("fma.rn.f32x2 %0, %1, %2, %0;" : "+l"(d) : "l"(a), "l"(b));
}
__device__ __forceinline__ u64 pack2(float lo, float hi) {
    u64 r; asm("mov.b64 %0, {%1, %2};" : "=l"(r) : "f"(lo), "f"(hi)); return r;
}
__device__ __forceinline__ void unpack2(u64 v, float &lo, float &hi) {
    asm("mov.b64 {%0, %1}, %2;" : "=f"(lo), "=f"(hi) : "l"(v));
}
__device__ __forceinline__ unsigned sm_u32(const void* p) {
    unsigned a;
    asm("{.reg .u64 t; cvta.to.shared.u64 t, %1; cvt.u32.u64 %0, t;}"
        : "=r"(a) : "l"(p));
    return a;
}

// ---------------------------------------------------------------------------
// Weight pre-format: [COUT][CIN][5] -> per-chunk [ci][k][{w,w} x co] dup pairs
// ---------------------------------------------------------------------------
__global__ void prep_weights(const float* __restrict__ w, float* __restrict__ dst,
                             int CIN, int COUT, int COUTP, int CHUNK)
{
    int idx = blockIdx.x * 256 + threadIdx.x;
    int n = COUT * CIN * 5;
    if (idx >= n) return;
    int co = idx / (CIN * 5), r = idx - co * (CIN * 5);
    int ci = r / 5, k = r - ci * 5;
    int q = ci / CHUNK, cil = ci - q * CHUNK;
    float v = w[idx];
    int o = q * (CHUNK * 10 * COUTP) + (cil * 5 + k) * 2 * COUTP + 2 * co;
    dst[o] = v; dst[o + 1] = v;
}

// ---------------------------------------------------------------------------
// Fused conv(dilated, reflect) + BN/bias + ReLU + linear x2 upsample.
// cp.async double-buffered chunk staging; packed f32x2 FMA; smem W broadcast.
// (R3-proven configuration.)
// ---------------------------------------------------------------------------
template<int CIN, int COUT, int DIL, int TL, int RC, int CHUNK>
__global__ __launch_bounds__(256, 2)
void conv_layer(const float* __restrict__ x,   // [B, CIN, L]
                const float* __restrict__ wp,  // prepped weights
                const float* __restrict__ gg,
                const float* __restrict__ bb,
                const float* __restrict__ mm,
                const float* __restrict__ vv,
                float* __restrict__ y,          // [B, COUT, 2L]
                int L)
{
    constexpr int PAD   = 2 * DIL;
    constexpr int SFT   = PAD + 4;
    constexpr int HALO  = TL + 2 * PAD + 5;
    constexpr int HALOP = (HALO + 3) & ~3;
    constexpr int NPG   = TL / 4;
    constexpr int COUTP = (COUT + 3) & ~3;
    constexpr int TLP   = TL + 4;
    constexpr int NQ    = (RC + 1) / 2;
    constexpr int WCH   = CHUNK * 10 * COUTP;
    constexpr int NCH   = CIN / CHUNK;

    const int tid  = threadIdx.x;
    const int tile = blockIdx.x;
    const int b    = blockIdx.y;
    const int pg   = tid % NPG;
    const int cg   = tid / NPG;
    const int lb   = pg * 4;
    const int cb   = cg * RC;

    extern __shared__ float sm[];
    float* Xbuf[2] = { sm, sm + CHUNK * HALOP };
    float* Wbuf[2] = { sm + 2 * CHUNK * HALOP, sm + 2 * CHUNK * HALOP + WCH };
    float* Ys  = sm + 2 * CHUNK * HALOP + 2 * WCH;   // COUT * TLP
    float* YsE = Ys + COUT * TLP;                    // COUT * 2

    const float* xb    = x + (size_t)b * CIN * L;
    const int    gbase = tile * TL - SFT;

    u64 acc[RC][2];
#pragma unroll
    for (int q = 0; q < RC; q++) { acc[q][0] = 0ull; acc[q][1] = 0ull; }

    float eacc = 0.f;
    const int eIdx = tid >> 1, eSide = tid & 1;
    int ej = 0;
    if (tid < 2 * COUT) {
        int gl = tile * TL + (eSide ? TL : -1);
        if (gl < 0)  gl = 0;
        if (gl >= L) gl = L - 1;
        ej = gl - tile * TL;
    }

    auto stage = [&](int p, int cc) {
        float* Xd = Xbuf[p];
        for (int idx = tid; idx < CHUNK * HALO; idx += 256) {
            int ci = idx / HALO, j = idx - ci * HALO;
            int gi = gbase + j;
            if (gi < 0)  gi = -gi;
            if (gi >= L) gi = 2 * L - 2 - gi;
            unsigned d = sm_u32(Xd + ci * HALOP + j);
            const float* s = xb + (size_t)(cc * CHUNK + ci) * L + gi;
            asm volatile("cp.async.ca.shared.global [%0], [%1], 4;" :: "r"(d), "l"(s));
        }
        const float4* wsrc = (const float4*)(wp + (size_t)cc * WCH);
        float* Wd = Wbuf[p];
        for (int idx = tid; idx < WCH / 4; idx += 256) {
            unsigned d = sm_u32(Wd + idx * 4);
            asm volatile("cp.async.cg.shared.global [%0], [%1], 16;"
                         :: "r"(d), "l"(wsrc + idx));
        }
        asm volatile("cp.async.commit_group;");
    };

    stage(0, 0);

    for (int cc = 0; cc < NCH; cc++) {
        const int p = cc & 1;
        asm volatile("cp.async.wait_group 0;");
        __syncthreads();
        if (cc + 1 < NCH) stage(p ^ 1, cc + 1);

        const float* Xs = Xbuf[p];
        const float* Ws = Wbuf[p];

#pragma unroll 2
        for (int ci = 0; ci < CHUNK; ci++) {
            const float* xr = Xs + ci * HALOP + lb + 4;
            if (DIL == 1) {
                float4 f0 = *(const float4*)xr;
                float4 f1 = *(const float4*)(xr + 4);
                float fv[8] = {f0.x, f0.y, f0.z, f0.w, f1.x, f1.y, f1.z, f1.w};
                u64 P[7];
#pragma unroll
                for (int i = 0; i < 7; i++) P[i] = pack2(fv[i], fv[i + 1]);
#pragma unroll
                for (int k = 0; k < 5; k++) {
                    u64 xp0 = P[k], xp1 = P[k + 2];
                    const float* wr = Ws + (ci * 5 + k) * 2 * COUTP + 2 * cb;
#pragma unroll
                    for (int qq = 0; qq < NQ; qq++) {
                        ulonglong2 wv = *(const ulonglong2*)(wr + 4 * qq);
                        fma2(acc[2 * qq][0], wv.x, xp0);
                        fma2(acc[2 * qq][1], wv.x, xp1);
                        if (2 * qq + 1 < RC) {
                            fma2(acc[2 * qq + 1][0], wv.y, xp0);
                            fma2(acc[2 * qq + 1][1], wv.y, xp1);
                        }
                    }
                }
            } else if (DIL == 2) {
                ulonglong2 e0 = *(const ulonglong2*)xr;
                ulonglong2 e1 = *(const ulonglong2*)(xr + 4);
                ulonglong2 e2 = *(const ulonglong2*)(xr + 8);
                u64 E[6] = {e0.x, e0.y, e1.x, e1.y, e2.x, e2.y};
#pragma unroll
                for (int k = 0; k < 5; k++) {
                    u64 xp0 = E[k], xp1 = E[k + 1];
                    const float* wr = Ws + (ci * 5 + k) * 2 * COUTP + 2 * cb;
#pragma unroll
                    for (int qq = 0; qq < NQ; qq++) {
                        ulonglong2 wv = *(const ulonglong2*)(wr + 4 * qq);
                        fma2(acc[2 * qq][0], wv.x, xp0);
                        fma2(acc[2 * qq][1], wv.x, xp1);
                        if (2 * qq + 1 < RC) {
                            fma2(acc[2 * qq + 1][0], wv.y, xp0);
                            fma2(acc[2 * qq + 1][1], wv.y, xp1);
                        }
                    }
                }
            } else {
#pragma unroll
                for (int k = 0; k < 5; k++) {
                    ulonglong2 xv = *(const ulonglong2*)(xr + k * DIL);
                    u64 xp0 = xv.x, xp1 = xv.y;
                    const float* wr = Ws + (ci * 5 + k) * 2 * COUTP + 2 * cb;
#pragma unroll
                    for (int qq = 0; qq < NQ; qq++) {
                        ulonglong2 wv = *(const ulonglong2*)(wr + 4 * qq);
                        fma2(acc[2 * qq][0], wv.x, xp0);
                        fma2(acc[2 * qq][1], wv.x, xp1);
                        if (2 * qq + 1 < RC) {
                            fma2(acc[2 * qq + 1][0], wv.y, xp0);
                            fma2(acc[2 * qq + 1][1], wv.y, xp1);
                        }
                    }
                }
            }
        }

        if (tid < 2 * COUT) {
#pragma unroll 1
            for (int ci = 0; ci < CHUNK; ci++)
#pragma unroll
                for (int k = 0; k < 5; k++)
                    eacc = fmaf(Ws[(ci * 5 + k) * 2 * COUTP + 2 * eIdx],
                                Xs[ci * HALOP + ej + 4 + k * DIL], eacc);
        }
    }

    // ---- BN + ReLU -> Ys ----
#pragma unroll
    for (int q = 0; q < RC; q++) {
        int c = cb + q;
        float inv = gg[c] * rsqrtf(vv[c] + 1e-5f);
        float sh  = bb[c] - mm[c] * inv;
        float a0, a1, a2, a3;
        unpack2(acc[q][0], a0, a1);
        unpack2(acc[q][1], a2, a3);
        a0 = fmaxf(a0 * inv + sh, 0.f); a1 = fmaxf(a1 * inv + sh, 0.f);
        a2 = fmaxf(a2 * inv + sh, 0.f); a3 = fmaxf(a3 * inv + sh, 0.f);
        *(float4*)(Ys + c * TLP + lb) = make_float4(a0, a1, a2, a3);
    }
    if (tid < 2 * COUT) {
        int c = eIdx;
        float inv = gg[c] * rsqrtf(vv[c] + 1e-5f);
        YsE[2 * c + eSide] = fmaxf(eacc * inv + bb[c] - mm[c] * inv, 0.f);
    }
    __syncthreads();

    // ---- linear x2 upsample + coalesced store ----
    const int Lup = 2 * L;
#pragma unroll
    for (int q = 0; q < RC; q++) {
        int c = cb + q;
        const float* row = Ys + c * TLP;
        float4 y4 = *(const float4*)(row + lb);
        float yl = lb ? row[lb - 1] : YsE[2 * c];
        float yr = (lb == TL - 4) ? YsE[2 * c + 1] : row[lb + 4];
        float o0 = 0.25f * yl   + 0.75f * y4.x, o1 = 0.75f * y4.x + 0.25f * y4.y;
        float o2 = 0.25f * y4.x + 0.75f * y4.y, o3 = 0.75f * y4.y + 0.25f * y4.z;
        float o4 = 0.25f * y4.y + 0.75f * y4.z, o5 = 0.75f * y4.z + 0.25f * y4.w;
        float o6 = 0.25f * y4.z + 0.75f * y4.w, o7 = 0.75f * y4.w + 0.25f * yr;
        size_t off = ((size_t)b * COUT + c) * Lup + 2 * (tile * TL + lb);
        *(float4*)(y + off)     = make_float4(o0, o1, o2, o3);
        *(float4*)(y + off + 4) = make_float4(o4, o5, o6, o7);
    }
}

// ---------------------------------------------------------------------------
// Fused final stage: conv(8->3, DIL=16, reflect) + bias + up2 + transpose to
// [bt][3][T][st] + masked CE loss. Block: one bt, 8 st rows, 256 pre-up pos.
// ---------------------------------------------------------------------------
#define FL    16384
#define FTL   256
#define FSFT  36
#define FHALO 325
#define FHALOP 328
#define STRD  516

__global__ __launch_bounds__(256)
void final_fused(const float* __restrict__ in,   // [B, 8, FL]
                 const float* __restrict__ w5,   // [3][8][5] raw
                 const float* __restrict__ bout, // [3]
                 const float* __restrict__ tg,
                 float* __restrict__ out,
                 double* accum, int* mask)
{
    const int tid  = threadIdx.x;
    const int tile = blockIdx.x;
    const int bt   = blockIdx.y;
    const int st   = tid >> 5;
    const int lane = tid & 31;
    const int lb   = lane * 8;

    extern __shared__ float sm[];
    float* Xs    = sm;                         // [8st*8ci][FHALOP]
    float* stg   = sm + 64 * FHALOP;           // [3*8][STRD]
    float* YsE2  = stg + 24 * STRD;            // [3*8][2]
    __shared__ float Wf[120];
    __shared__ float red[256];

    if (tid < 120) Wf[tid] = w5[tid];
    const int gbase = tile * FTL - FSFT;
    for (int idx = tid; idx < 64 * FHALO; idx += 256) {
        int r = idx / FHALO, j = idx - r * FHALO;
        int gi = gbase + j;
        if (gi < 0)   gi = -gi;
        if (gi >= FL) gi = 2 * FL - 2 - gi;
        Xs[r * FHALOP + j] = in[(size_t)(bt * 64 + r) * FL + gi];
    }
    __syncthreads();

    float a[3][8];
#pragma unroll
    for (int c = 0; c < 3; c++)
#pragma unroll
        for (int j = 0; j < 8; j++) a[c][j] = 0.f;

    const float* xs_st = Xs + (st * 8) * FHALOP;
#pragma unroll 2
    for (int ci = 0; ci < 8; ci++) {
        const float* xr = xs_st + ci * FHALOP + lb + 4;
#pragma unroll
        for (int k = 0; k < 5; k++) {
            float4 xa = *(const float4*)(xr + 16 * k);
            float4 xb2 = *(const float4*)(xr + 16 * k + 4);
            float xv[8] = {xa.x, xa.y, xa.z, xa.w, xb2.x, xb2.y, xb2.z, xb2.w};
#pragma unroll
            for (int c = 0; c < 3; c++) {
                float wv = Wf[(c * 8 + ci) * 5 + k];
#pragma unroll
                for (int j = 0; j < 8; j++) a[c][j] = fmaf(wv, xv[j], a[c][j]);
            }
        }
    }

    // tile-edge conv values
    if (tid < 48) {
        int st_e = tid / 6, r6 = tid % 6;
        int c_e = r6 >> 1, side = r6 & 1;
        int gl = tile * FTL + (side ? FTL : -1);
        if (gl < 0)   gl = 0;
        if (gl >= FL) gl = FL - 1;
        int jj = gl - tile * FTL + 4;
        float s = 0.f;
#pragma unroll 1
        for (int ci = 0; ci < 8; ci++)
#pragma unroll
            for (int k = 0; k < 5; k++)
                s = fmaf(Wf[(c_e * 8 + ci) * 5 + k],
                         Xs[(st_e * 8 + ci) * FHALOP + jj + 16 * k], s);
        YsE2[(c_e * 8 + st_e) * 2 + side] = s + bout[c_e];
    }
    __syncthreads();

    // bias + upsample + write transpose-staging tile
#pragma unroll
    for (int c = 0; c < 3; c++) {
        float bC = bout[c];
#pragma unroll
        for (int j = 0; j < 8; j++) a[c][j] += bC;
        float yl = __shfl_up_sync(0xffffffffu, a[c][7], 1);
        float yr = __shfl_down_sync(0xffffffffu, a[c][0], 1);
        if (lane == 0)  yl = YsE2[(c * 8 + st) * 2];
        if (lane == 31) yr = YsE2[(c * 8 + st) * 2 + 1];
        float o[16];
        o[0] = 0.25f * yl + 0.75f * a[c][0];
#pragma unroll
        for (int j = 1; j < 8; j++) o[2 * j] = 0.25f * a[c][j - 1] + 0.75f * a[c][j];
#pragma unroll
        for (int j = 0; j < 7; j++) o[2 * j + 1] = 0.75f * a[c][j] + 0.25f * a[c][j + 1];
        o[15] = 0.75f * a[c][7] + 0.25f * yr;
        float* sp = stg + (c * 8 + st) * STRD + 2 * lb;
#pragma unroll
        for (int i = 0; i < 4; i++)
            *(float4*)(sp + 4 * i) = make_float4(o[4 * i], o[4 * i + 1],
                                                 o[4 * i + 2], o[4 * i + 3]);
    }
    __syncthreads();

    // coalesced transposed output + loss
    const size_t cs   = (size_t)NT_OUT * 8;
    const size_t base = ((size_t)bt * 3 * NT_OUT + (size_t)tile * 512) * 8;
    float s = 0.f;
    bool nz = false;
#pragma unroll 4
    for (int i = 0; i < 16; i++) {
        int f = i * 256 + tid;
        int t = f >> 3, stt = f & 7;
        float o0 = stg[(0 * 8 + stt) * STRD + t];
        float o1 = stg[(1 * 8 + stt) * STRD + t];
        float o2 = stg[(2 * 8 + stt) * STRD + t];
        out[base + f]          = o0;
        out[base + cs + f]     = o1;
        out[base + 2 * cs + f] = o2;
        float t0v = tg[base + f], t1v = tg[base + cs + f], t2v = tg[base + 2 * cs + f];
        float mx  = fmaxf(o0, fmaxf(o1, o2));
        float lse = mx + __logf(__expf(o0 - mx) + __expf(o1 - mx) + __expf(o2 - mx));
        s += t0v * (lse - o0) + t1v * (lse - o1) + t2v * (lse - o2);
        nz = nz || (t0v != 0.f) || (t1v != 0.f) || (t2v != 0.f);
    }
    if (nz) atomicOr(&mask[bt * 8 + (tid & 7)], 1);

    red[tid] = s;
    __syncthreads();
    for (int o = 128; o > 0; o >>= 1) {
        if (tid < o) red[tid] += red[tid + o];
        __syncthreads();
    }
    if (tid == 0) atomicAdd(accum, (double)red[0]);
}

__global__ void init_kernel(double* accum, int* mask)
{
    if (threadIdx.x == 0) *accum = 0.0;
    if (threadIdx.x < BATCH) mask[threadIdx.x] = 0;
}

__global__ void finalize_kernel(const double* accum, const int* mask,
                                float* out, int out_size)
{
    if (threadIdx.x != 0 || blockIdx.x != 0) return;
    int num = 0;
    for (int i = 0; i < BATCH; i++) num += (mask[i] ? 1 : 0);
    double loss = *accum / ((double)num * (double)NT_OUT);
    if ((unsigned)out_size > OUT_ELEMS) out[OUT_ELEMS] = (float)loss;
}

// ---------------------------------------------------------------------------
static constexpr int conv_smem(int CIN, int COUT, int DIL, int TL, int CHUNK) {
    int halop = ((TL + 4 * DIL + 5) + 3) & ~3;
    int coutp = (COUT + 3) & ~3;
    return (2 * CHUNK * halop + 2 * CHUNK * 10 * coutp + COUT * (TL + 4) + COUT * 2) * 4;
}

extern "C" void kernel_launch(void* const* d_in, const int* in_sizes, int n_in,
                              void* d_out, int out_size)
{
    const float* x  = (const float*)d_in[0];
    const float* tg = (const float*)d_in[1];
    const float *w[5], *g[4], *bb[4], *mm[4], *vv[4], *b_out;

    bool inter = (n_in > 3) && (in_sizes[3] == 64);
    if (inter) {
        for (int i = 0; i < 4; i++) {
            w[i]  = (const float*)d_in[2 + 5 * i];
            g[i]  = (const float*)d_in[3 + 5 * i];
            bb[i] = (const float*)d_in[4 + 5 * i];
            mm[i] = (const float*)d_in[5 + 5 * i];
            vv[i] = (const float*)d_in[6 + 5 * i];
        }
    } else {
        for (int i = 0; i < 4; i++) {
            w[i]  = (const float*)d_in[2 + i];
            g[i]  = (const float*)d_in[6 + i];
            bb[i] = (const float*)d_in[10 + i];
            mm[i] = (const float*)d_in[14 + i];
            vv[i] = (const float*)d_in[18 + i];
        }
    }
    w[4]  = (const float*)d_in[22];
    b_out = (const float*)d_in[23];

    float *bufA, *bufB, *wprep;
    double* accum;
    int* mask;
    cudaGetSymbolAddress((void**)&bufA, g_bufA);
    cudaGetSymbolAddress((void**)&bufB, g_bufB);
    cudaGetSymbolAddress((void**)&wprep, g_wprep);
    cudaGetSymbolAddress((void**)&accum, g_loss_accum);
    cudaGetSymbolAddress((void**)&mask, g_mask);

    // prepped-weight offsets: CIN*10*COUTP floats per layer
    const size_t o0 = 0;
    const size_t o1 = o0 + (size_t)128 * 10 * 64;  // 81920
    const size_t o2 = o1 + (size_t)64 * 10 * 32;   // 102400
    const size_t o3 = o2 + (size_t)32 * 10 * 16;   // 107520

    prep_weights<<<(64 * 128 * 5 + 255) / 256, 256>>>(w[0], wprep + o0, 128, 64, 64, 8);
    prep_weights<<<(32 * 64 * 5 + 255) / 256, 256>>>(w[1], wprep + o1, 64, 32, 32, 8);
    prep_weights<<<(16 * 32 * 5 + 255) / 256, 256>>>(w[2], wprep + o2, 32, 16, 16, 8);
    prep_weights<<<(8 * 16 * 5 + 255) / 256, 256>>>(w[3], wprep + o3, 16, 8, 8, 8);

    constexpr int SM0 = conv_smem(128, 64, 1, 128, 8);
    constexpr int SM1 = conv_smem(64, 32, 2, 256, 8);
    constexpr int SM2 = conv_smem(32, 16, 4, 512, 8);
    constexpr int SM3 = conv_smem(16, 8, 8, 1024, 8);
    constexpr int SMF = (64 * FHALOP + 24 * STRD + 48) * 4;

    cudaFuncSetAttribute(conv_layer<128, 64, 1, 128, 8, 8>,
                         cudaFuncAttributeMaxDynamicSharedMemorySize, SM0);
    cudaFuncSetAttribute(conv_layer<64, 32, 2, 256, 8, 8>,
                         cudaFuncAttributeMaxDynamicSharedMemorySize, SM1);
    cudaFuncSetAttribute(conv_layer<32, 16, 4, 512, 8, 8>,
                         cudaFuncAttributeMaxDynamicSharedMemorySize, SM2);
    cudaFuncSetAttribute(conv_layer<16, 8, 8, 1024, 8, 8>,
                         cudaFuncAttributeMaxDynamicSharedMemorySize, SM3);
    cudaFuncSetAttribute(final_fused,
                         cudaFuncAttributeMaxDynamicSharedMemorySize, SMF);

    init_kernel<<<1, 256>>>(accum, mask);

    conv_layer<128, 64, 1, 128, 8, 8>
        <<<dim3(1024 / 128, BATCH), 256, SM0>>>(x, wprep + o0, g[0], bb[0], mm[0], vv[0],
                                                bufA, 1024);
    conv_layer<64, 32, 2, 256, 8, 8>
        <<<dim3(2048 / 256, BATCH), 256, SM1>>>(bufA, wprep + o1, g[1], bb[1], mm[1], vv[1],
                                                bufB, 2048);
    conv_layer<32, 16, 4, 512, 8, 8>
        <<<dim3(4096 / 512, BATCH), 256, SM2>>>(bufB, wprep + o2, g[2], bb[2], mm[2], vv[2],
                                                bufA, 4096);
    conv_layer<16, 8, 8, 1024, 8, 8>
        <<<dim3(8192 / 1024, BATCH), 256, SM3>>>(bufA, wprep + o3, g[3], bb[3], mm[3], vv[3],
                                                 bufB, 8192);

    final_fused<<<dim3(FL / FTL, 32), 256, SMF>>>(bufB, w[4], b_out, tg,
                                                  (float*)d_out, accum, mask);
    finalize_kernel<<<1, 1>>>(accum, mask, (float*)d_out, out_size);
}

// round 9
// speedup vs baseline: 1.1533x; 1.1533x over previous
#include <cuda_runtime.h>
#include <stdint.h>
#include <math.h>

#define BATCH 256
#define NT_OUT 32768
#define OUT_ELEMS (32u * 3u * 32768u * 8u)   // 25,165,824

// scratch — __device__ globals, no allocs
__device__ float g_bufA[BATCH * 64 * 2048];
__device__ float g_bufB[BATCH * 64 * 2048];
__device__ float g_wprep[131072];
__device__ double g_loss_accum;
__device__ int    g_mask[BATCH];

typedef unsigned long long u64;

__device__ __forceinline__ void fma2(u64 &d, u64 a, u64 b) {
    asm("fma.rn.f32x2 %0, %1, %2, %0;" : "+l"(d) : "l"(a), "l"(b));
}
__device__ __forceinline__ u64 pack2(float lo, float hi) {
    u64 r; asm("mov.b64 %0, {%1, %2};" : "=l"(r) : "f"(lo), "f"(hi)); return r;
}
__device__ __forceinline__ void unpack2(u64 v, float &lo, float &hi) {
    asm("mov.b64 {%0, %1}, %2;" : "=f"(lo), "=f"(hi) : "l"(v));
}
__device__ __forceinline__ unsigned sm_u32(const void* p) {
    unsigned a;
    asm("{.reg .u64 t; cvta.to.shared.u64 t, %1; cvt.u32.u64 %0, t;}"
        : "=r"(a) : "l"(p));
    return a;
}

// ---------------------------------------------------------------------------
// Weight pre-format: [COUT][CIN][5] -> per-chunk [ci][k][{w,w} x co] dup pairs
// ---------------------------------------------------------------------------
__global__ void prep_weights(const float* __restrict__ w, float* __restrict__ dst,
                             int CIN, int COUT, int COUTP, int CHUNK)
{
    int idx = blockIdx.x * 256 + threadIdx.x;
    int n = COUT * CIN * 5;
    if (idx >= n) return;
    int co = idx / (CIN * 5), r = idx - co * (CIN * 5);
    int ci = r / 5, k = r - ci * 5;
    int q = ci / CHUNK, cil = ci - q * CHUNK;
    float v = w[idx];
    int o = q * (CHUNK * 10 * COUTP) + (cil * 5 + k) * 2 * COUTP + 2 * co;
    dst[o] = v; dst[o + 1] = v;
}

// ---------------------------------------------------------------------------
// Fused conv(dilated, reflect) + BN/bias + ReLU + linear x2 upsample.
// cp.async double-buffered staging; f32x2 FMA; smem W broadcast (R3-proven).
// NEW: shuffle-based upsample epilogue (no Ys tile) + 3 CTAs/SM.
// ---------------------------------------------------------------------------
template<int CIN, int COUT, int DIL, int TL, int RC, int CHUNK, bool BN, bool FINAL>
__global__ __launch_bounds__(256, 3)
void conv_layer(const float* __restrict__ x,   // [B, CIN, L]
                const float* __restrict__ wp,  // prepped weights
                const float* __restrict__ gg,
                const float* __restrict__ bb,
                const float* __restrict__ mm,
                const float* __restrict__ vv,
                const float* __restrict__ bout,
                float* __restrict__ y,          // [B, COUT, 2L]
                int L)
{
    constexpr int PAD   = 2 * DIL;
    constexpr int SFT   = PAD + 4;
    constexpr int HALO  = TL + 2 * PAD + 5;
    constexpr int HALOP = (HALO + 3) & ~3;
    constexpr int NPG   = TL / 4;
    constexpr int COUTP = (COUT + 3) & ~3;
    constexpr int NQ    = (RC + 1) / 2;
    constexpr int WCH   = CHUNK * 10 * COUTP;
    constexpr int NCH   = CIN / CHUNK;
    constexpr int WPC   = NPG / 32;             // warps per cout-group

    const int tid  = threadIdx.x;
    const int tile = blockIdx.x;
    const int b    = blockIdx.y;
    const int pg   = tid % NPG;
    const int cg   = tid / NPG;
    const int lane = tid & 31;
    const int wic  = pg >> 5;
    const int lb   = pg * 4;
    const int cb   = cg * RC;

    extern __shared__ float sm[];
    float* Xbuf[2] = { sm, sm + CHUNK * HALOP };
    float* Wbuf[2] = { sm + 2 * CHUNK * HALOP, sm + 2 * CHUNK * HALOP + WCH };
    float* YsE   = sm + 2 * CHUNK * HALOP + 2 * WCH;   // [COUT][2]
    float* BndA3 = YsE + 2 * COUT;                     // [COUT][WPC] last pos of warp
    float* BndA0 = BndA3 + COUT * WPC;                 // [COUT][WPC] first pos of warp

    const float* xb    = x + (size_t)b * CIN * L;
    const int    gbase = tile * TL - SFT;

    u64 acc[RC][2];
#pragma unroll
    for (int q = 0; q < RC; q++) { acc[q][0] = 0ull; acc[q][1] = 0ull; }

    float eacc = 0.f;
    const int eIdx = tid >> 1, eSide = tid & 1;
    int ej = 0;
    if (tid < 2 * COUT) {
        int gl = tile * TL + (eSide ? TL : -1);
        if (gl < 0)  gl = 0;
        if (gl >= L) gl = L - 1;
        ej = gl - tile * TL;
    }

    auto stage = [&](int p, int cc) {
        float* Xd = Xbuf[p];
        for (int idx = tid; idx < CHUNK * HALO; idx += 256) {
            int ci = idx / HALO, j = idx - ci * HALO;
            int gi = gbase + j;
            if (gi < 0)  gi = -gi;
            if (gi >= L) gi = 2 * L - 2 - gi;
            unsigned d = sm_u32(Xd + ci * HALOP + j);
            const float* s = xb + (size_t)(cc * CHUNK + ci) * L + gi;
            asm volatile("cp.async.ca.shared.global [%0], [%1], 4;" :: "r"(d), "l"(s));
        }
        const float4* wsrc = (const float4*)(wp + (size_t)cc * WCH);
        float* Wd = Wbuf[p];
        for (int idx = tid; idx < WCH / 4; idx += 256) {
            unsigned d = sm_u32(Wd + idx * 4);
            asm volatile("cp.async.cg.shared.global [%0], [%1], 16;"
                         :: "r"(d), "l"(wsrc + idx));
        }
        asm volatile("cp.async.commit_group;");
    };

    stage(0, 0);

    for (int cc = 0; cc < NCH; cc++) {
        const int p = cc & 1;
        asm volatile("cp.async.wait_group 0;");
        __syncthreads();
        if (cc + 1 < NCH) stage(p ^ 1, cc + 1);

        const float* Xs = Xbuf[p];
        const float* Ws = Wbuf[p];

#pragma unroll 2
        for (int ci = 0; ci < CHUNK; ci++) {
            const float* xr = Xs + ci * HALOP + lb + 4;
            if (DIL == 1) {
                float4 f0 = *(const float4*)xr;
                float4 f1 = *(const float4*)(xr + 4);
                float fv[8] = {f0.x, f0.y, f0.z, f0.w, f1.x, f1.y, f1.z, f1.w};
                u64 P[7];
#pragma unroll
                for (int i = 0; i < 7; i++) P[i] = pack2(fv[i], fv[i + 1]);
#pragma unroll
                for (int k = 0; k < 5; k++) {
                    u64 xp0 = P[k], xp1 = P[k + 2];
                    const float* wr = Ws + (ci * 5 + k) * 2 * COUTP + 2 * cb;
#pragma unroll
                    for (int qq = 0; qq < NQ; qq++) {
                        ulonglong2 wv = *(const ulonglong2*)(wr + 4 * qq);
                        fma2(acc[2 * qq][0], wv.x, xp0);
                        fma2(acc[2 * qq][1], wv.x, xp1);
                        if (2 * qq + 1 < RC) {
                            fma2(acc[2 * qq + 1][0], wv.y, xp0);
                            fma2(acc[2 * qq + 1][1], wv.y, xp1);
                        }
                    }
                }
            } else if (DIL == 2) {
                ulonglong2 e0 = *(const ulonglong2*)xr;
                ulonglong2 e1 = *(const ulonglong2*)(xr + 4);
                ulonglong2 e2 = *(const ulonglong2*)(xr + 8);
                u64 E[6] = {e0.x, e0.y, e1.x, e1.y, e2.x, e2.y};
#pragma unroll
                for (int k = 0; k < 5; k++) {
                    u64 xp0 = E[k], xp1 = E[k + 1];
                    const float* wr = Ws + (ci * 5 + k) * 2 * COUTP + 2 * cb;
#pragma unroll
                    for (int qq = 0; qq < NQ; qq++) {
                        ulonglong2 wv = *(const ulonglong2*)(wr + 4 * qq);
                        fma2(acc[2 * qq][0], wv.x, xp0);
                        fma2(acc[2 * qq][1], wv.x, xp1);
                        if (2 * qq + 1 < RC) {
                            fma2(acc[2 * qq + 1][0], wv.y, xp0);
                            fma2(acc[2 * qq + 1][1], wv.y, xp1);
                        }
                    }
                }
            } else {
#pragma unroll
                for (int k = 0; k < 5; k++) {
                    ulonglong2 xv = *(const ulonglong2*)(xr + k * DIL);
                    u64 xp0 = xv.x, xp1 = xv.y;
                    const float* wr = Ws + (ci * 5 + k) * 2 * COUTP + 2 * cb;
#pragma unroll
                    for (int qq = 0; qq < NQ; qq++) {
                        ulonglong2 wv = *(const ulonglong2*)(wr + 4 * qq);
                        fma2(acc[2 * qq][0], wv.x, xp0);
                        fma2(acc[2 * qq][1], wv.x, xp1);
                        if (2 * qq + 1 < RC) {
                            fma2(acc[2 * qq + 1][0], wv.y, xp0);
                            fma2(acc[2 * qq + 1][1], wv.y, xp1);
                        }
                    }
                }
            }
        }

        if (tid < 2 * COUT) {
#pragma unroll 1
            for (int ci = 0; ci < CHUNK; ci++)
#pragma unroll
                for (int k = 0; k < 5; k++)
                    eacc = fmaf(Ws[(ci * 5 + k) * 2 * COUTP + 2 * eIdx],
                                Xs[ci * HALOP + ej + 4 + k * DIL], eacc);
        }
    }

    // ---- BN/bias (+ReLU) into registers; publish warp-boundary values ----
    float v[RC][4];
#pragma unroll
    for (int q = 0; q < RC; q++) {
        int c = cb + q;
        float sc, sh;
        if (FINAL) { sc = 1.f; sh = bout[c]; }
        else {
            float inv = gg[c] * rsqrtf(vv[c] + 1e-5f);
            sc = inv; sh = bb[c] - mm[c] * inv;
        }
        float a0, a1, a2, a3;
        unpack2(acc[q][0], a0, a1);
        unpack2(acc[q][1], a2, a3);
        a0 = a0 * sc + sh; a1 = a1 * sc + sh;
        a2 = a2 * sc + sh; a3 = a3 * sc + sh;
        if (BN) {
            a0 = fmaxf(a0, 0.f); a1 = fmaxf(a1, 0.f);
            a2 = fmaxf(a2, 0.f); a3 = fmaxf(a3, 0.f);
        }
        v[q][0] = a0; v[q][1] = a1; v[q][2] = a2; v[q][3] = a3;
        if (lane == 31) BndA3[c * WPC + wic] = a3;
        if (lane == 0)  BndA0[c * WPC + wic] = a0;
    }
    if (tid < 2 * COUT) {
        int c = eIdx;
        float sc, sh;
        if (FINAL) { sc = 1.f; sh = bout[c]; }
        else {
            float inv = gg[c] * rsqrtf(vv[c] + 1e-5f);
            sc = inv; sh = bb[c] - mm[c] * inv;
        }
        float val = eacc * sc + sh;
        if (BN) val = fmaxf(val, 0.f);
        YsE[2 * c + eSide] = val;
    }
    __syncthreads();

    // ---- shuffle-based x2 upsample + coalesced store ----
    const int Lup = 2 * L;
#pragma unroll
    for (int q = 0; q < RC; q++) {
        int c = cb + q;
        float yl = __shfl_up_sync(0xffffffffu, v[q][3], 1);
        float yr = __shfl_down_sync(0xffffffffu, v[q][0], 1);
        if (lane == 0)  yl = (wic == 0)       ? YsE[2 * c]     : BndA3[c * WPC + wic - 1];
        if (lane == 31) yr = (wic == WPC - 1) ? YsE[2 * c + 1] : BndA0[c * WPC + wic + 1];
        float y0 = v[q][0], y1 = v[q][1], y2 = v[q][2], y3 = v[q][3];
        float o0 = 0.25f * yl + 0.75f * y0, o1 = 0.75f * y0 + 0.25f * y1;
        float o2 = 0.25f * y0 + 0.75f * y1, o3 = 0.75f * y1 + 0.25f * y2;
        float o4 = 0.25f * y1 + 0.75f * y2, o5 = 0.75f * y2 + 0.25f * y3;
        float o6 = 0.25f * y2 + 0.75f * y3, o7 = 0.75f * y3 + 0.25f * yr;
        size_t off = ((size_t)b * COUT + c) * Lup + 2 * (tile * TL + lb);
        *(float4*)(y + off)     = make_float4(o0, o1, o2, o3);
        *(float4*)(y + off + 4) = make_float4(o4, o5, o6, o7);
    }
}

// ---------------------------------------------------------------------------
// Transpose [b=bt*8+st][3][T] -> [bt][3][T][st] + fused masked CE loss.
// ---------------------------------------------------------------------------
#define TT 512
#define TTP 516
__global__ __launch_bounds__(256)
void transpose_loss(const float* __restrict__ in, const float* __restrict__ tg,
                    float* __restrict__ out, double* accum, int* mask)
{
    const int bt = blockIdx.y;
    const int t0 = blockIdx.x * TT;
    const int tid = threadIdx.x;
    extern __shared__ float tile[];               // [3][8][TTP]

    for (int idx = tid; idx < 3 * 8 * TT; idx += 256) {
        int c = idx / (8 * TT), r = idx - c * (8 * TT);
        int st = r / TT, t = r - st * TT;
        tile[(c * 8 + st) * TTP + t] =
            in[((size_t)(bt * 8 + st) * 3 + c) * NT_OUT + t0 + t];
    }
    __syncthreads();

    float s = 0.f;
    bool nz = false;
    const size_t ob = ((size_t)bt * 3) * NT_OUT * 8 + (size_t)t0 * 8;
    const size_t cs = (size_t)NT_OUT * 8;
#pragma unroll 4
    for (int i = 0; i < (TT * 8) / 256; i++) {
        int f = i * 256 + tid;
        int t = f >> 3, st = f & 7;
        float o0 = tile[(0 * 8 + st) * TTP + t];
        float o1 = tile[(1 * 8 + st) * TTP + t];
        float o2 = tile[(2 * 8 + st) * TTP + t];
        out[ob + f]          = o0;
        out[ob + cs + f]     = o1;
        out[ob + 2 * cs + f] = o2;
        float t0v = tg[ob + f], t1v = tg[ob + cs + f], t2v = tg[ob + 2 * cs + f];
        float mx  = fmaxf(o0, fmaxf(o1, o2));
        float lse = mx + __logf(__expf(o0 - mx) + __expf(o1 - mx) + __expf(o2 - mx));
        s += t0v * (lse - o0) + t1v * (lse - o1) + t2v * (lse - o2);
        nz = nz || (t0v != 0.f) || (t1v != 0.f) || (t2v != 0.f);
    }
    if (nz) atomicOr(&mask[bt * 8 + (tid & 7)], 1);

    __shared__ float red[256];
    red[tid] = s;
    __syncthreads();
    for (int o = 128; o > 0; o >>= 1) {
        if (tid < o) red[tid] += red[tid + o];
        __syncthreads();
    }
    if (tid == 0) atomicAdd(accum, (double)red[0]);
}

__global__ void init_kernel(double* accum, int* mask)
{
    if (threadIdx.x == 0) *accum = 0.0;
    if (threadIdx.x < BATCH) mask[threadIdx.x] = 0;
}

__global__ void finalize_kernel(const double* accum, const int* mask,
                                float* out, int out_size)
{
    if (threadIdx.x != 0 || blockIdx.x != 0) return;
    int num = 0;
    for (int i = 0; i < BATCH; i++) num += (mask[i] ? 1 : 0);
    double loss = *accum / ((double)num * (double)NT_OUT);
    if ((unsigned)out_size > OUT_ELEMS) out[OUT_ELEMS] = (float)loss;
}

// ---------------------------------------------------------------------------
static constexpr int conv_smem(int CIN, int COUT, int DIL, int TL, int CHUNK) {
    int halop = ((TL + 4 * DIL + 5) + 3) & ~3;
    int coutp = (COUT + 3) & ~3;
    int wpc = (TL / 4) / 32;
    return (2 * CHUNK * halop + 2 * CHUNK * 10 * coutp + 2 * COUT + 2 * COUT * wpc) * 4;
}

extern "C" void kernel_launch(void* const* d_in, const int* in_sizes, int n_in,
                              void* d_out, int out_size)
{
    const float* x  = (const float*)d_in[0];
    const float* tg = (const float*)d_in[1];
    const float *w[5], *g[4], *bb[4], *mm[4], *vv[4], *b_out;

    bool inter = (n_in > 3) && (in_sizes[3] == 64);
    if (inter) {
        for (int i = 0; i < 4; i++) {
            w[i]  = (const float*)d_in[2 + 5 * i];
            g[i]  = (const float*)d_in[3 + 5 * i];
            bb[i] = (const float*)d_in[4 + 5 * i];
            mm[i] = (const float*)d_in[5 + 5 * i];
            vv[i] = (const float*)d_in[6 + 5 * i];
        }
    } else {
        for (int i = 0; i < 4; i++) {
            w[i]  = (const float*)d_in[2 + i];
            g[i]  = (const float*)d_in[6 + i];
            bb[i] = (const float*)d_in[10 + i];
            mm[i] = (const float*)d_in[14 + i];
            vv[i] = (const float*)d_in[18 + i];
        }
    }
    w[4]  = (const float*)d_in[22];
    b_out = (const float*)d_in[23];

    float *bufA, *bufB, *wprep;
    double* accum;
    int* mask;
    cudaGetSymbolAddress((void**)&bufA, g_bufA);
    cudaGetSymbolAddress((void**)&bufB, g_bufB);
    cudaGetSymbolAddress((void**)&wprep, g_wprep);
    cudaGetSymbolAddress((void**)&accum, g_loss_accum);
    cudaGetSymbolAddress((void**)&mask, g_mask);

    // prepped-weight offsets (floats): CIN*10*COUTP per layer
    const size_t o0 = 0;
    const size_t o1 = o0 + (size_t)128 * 10 * 64;  //  81920
    const size_t o2 = o1 + (size_t)64 * 10 * 32;   // 102400
    const size_t o3 = o2 + (size_t)32 * 10 * 16;   // 107520
    const size_t o4 = o3 + (size_t)16 * 10 * 8;    // 108800  (L4: 8*10*4=320)

    prep_weights<<<(64 * 128 * 5 + 255) / 256, 256>>>(w[0], wprep + o0, 128, 64, 64, 8);
    prep_weights<<<(32 * 64 * 5 + 255) / 256, 256>>>(w[1], wprep + o1, 64, 32, 32, 8);
    prep_weights<<<(16 * 32 * 5 + 255) / 256, 256>>>(w[2], wprep + o2, 32, 16, 16, 8);
    prep_weights<<<(8 * 16 * 5 + 255) / 256, 256>>>(w[3], wprep + o3, 16, 8, 8, 8);
    prep_weights<<<(3 * 8 * 5 + 255) / 256, 256>>>(w[4], wprep + o4, 8, 3, 4, 8);

    constexpr int SM0 = conv_smem(128, 64, 1, 128, 8);
    constexpr int SM1 = conv_smem(64, 32, 2, 256, 8);
    constexpr int SM2 = conv_smem(32, 16, 4, 512, 8);
    constexpr int SM3 = conv_smem(16, 8, 8, 1024, 8);
    constexpr int SM4 = conv_smem(8, 3, 16, 1024, 8);
    constexpr int SMT = 3 * 8 * TTP * 4;

    cudaFuncSetAttribute(conv_layer<128, 64, 1, 128, 8, 8, true, false>,
                         cudaFuncAttributeMaxDynamicSharedMemorySize, SM0);
    cudaFuncSetAttribute(conv_layer<64, 32, 2, 256, 8, 8, true, false>,
                         cudaFuncAttributeMaxDynamicSharedMemorySize, SM1);
    cudaFuncSetAttribute(conv_layer<32, 16, 4, 512, 8, 8, true, false>,
                         cudaFuncAttributeMaxDynamicSharedMemorySize, SM2);
    cudaFuncSetAttribute(conv_layer<16, 8, 8, 1024, 8, 8, true, false>,
                         cudaFuncAttributeMaxDynamicSharedMemorySize, SM3);
    cudaFuncSetAttribute(conv_layer<8, 3, 16, 1024, 3, 8, false, true>,
                         cudaFuncAttributeMaxDynamicSharedMemorySize, SM4);
    cudaFuncSetAttribute(transpose_loss,
                         cudaFuncAttributeMaxDynamicSharedMemorySize, SMT);

    init_kernel<<<1, 256>>>(accum, mask);

    conv_layer<128, 64, 1, 128, 8, 8, true, false>
        <<<dim3(1024 / 128, BATCH), 256, SM0>>>(x, wprep + o0, g[0], bb[0], mm[0], vv[0],
                                                nullptr, bufA, 1024);
    conv_layer<64, 32, 2, 256, 8, 8, true, false>
        <<<dim3(2048 / 256, BATCH), 256, SM1>>>(bufA, wprep + o1, g[1], bb[1], mm[1], vv[1],
                                                nullptr, bufB, 2048);
    conv_layer<32, 16, 4, 512, 8, 8, true, false>
        <<<dim3(4096 / 512, BATCH), 256, SM2>>>(bufB, wprep + o2, g[2], bb[2], mm[2], vv[2],
                                                nullptr, bufA, 4096);
    conv_layer<16, 8, 8, 1024, 8, 8, true, false>
        <<<dim3(8192 / 1024, BATCH), 256, SM3>>>(bufA, wprep + o3, g[3], bb[3], mm[3], vv[3],
                                                 nullptr, bufB, 8192);
    conv_layer<8, 3, 16, 1024, 3, 8, false, true>
        <<<dim3(16384 / 1024, BATCH), 256, SM4>>>(bufB, wprep + o4, nullptr, nullptr, nullptr,
                                                  nullptr, b_out, bufA, 16384);

    transpose_loss<<<dim3(NT_OUT / TT, 32), 256, SMT>>>(bufA, tg, (float*)d_out,
                                                        accum, mask);
    finalize_kernel<<<1, 1>>>(accum, mask, (float*)d_out, out_size);
}